// round 10
// baseline (speedup 1.0000x reference)
#include <cuda_runtime.h>
#include <cuda_bf16.h>
#include <math.h>
#include <stdint.h>

// Problem constants
#define BB   2
#define SS   2048
#define DD   4096
#define HH   32
#define KVH  8
#define HD   128
#define SWW  4096
#define MM   (BB*SS)          // 4096 rows
#define NEGV (-1.0e9f)
#define SCALE (0.08838834764831845f)  // 128^-0.5

// ---------------- scratch (module-static, no runtime alloc) ----------------
__device__ float g_q[(size_t)MM * (HH*HD)];      // 4096 x 4096
__device__ float g_k[(size_t)MM * (KVH*HD)];     // 4096 x 1024
__device__ float g_v[(size_t)MM * (KVH*HD)];     // 4096 x 1024
__device__ float g_attn[(size_t)MM * (HH*HD)];   // 4096 x 4096

__device__ __forceinline__ uint32_t f2tf32(float f) {
    uint32_t r;
    asm("cvt.rna.tf32.f32 %0, %1;" : "=r"(r) : "f"(f));
    return r;
}
// pack (x -> low half, y -> high half) as bf16x2
__device__ __forceinline__ uint32_t pack_bf16(float x, float y) {
    uint32_t r;
    asm("cvt.rn.bf16x2.f32 %0, %1, %2;" : "=r"(r) : "f"(y), "f"(x));
    return r;
}
__device__ __forceinline__ float bf16_round(float x) {
    return __bfloat162float(__float2bfloat16(x));
}

#define MMA_TF32(d, a0,a1,a2,a3, b0,b1) \
    asm volatile("mma.sync.aligned.m16n8k8.row.col.f32.tf32.tf32.f32 " \
        "{%0,%1,%2,%3}, {%4,%5,%6,%7}, {%8,%9}, {%0,%1,%2,%3};" \
        : "+f"(d[0]),"+f"(d[1]),"+f"(d[2]),"+f"(d[3]) \
        : "r"(a0),"r"(a1),"r"(a2),"r"(a3),"r"(b0),"r"(b1))

#define MMA_BF16(d, a0,a1,a2,a3, b0,b1) \
    asm volatile("mma.sync.aligned.m16n8k16.row.col.f32.bf16.bf16.f32 " \
        "{%0,%1,%2,%3}, {%4,%5,%6,%7}, {%8,%9}, {%0,%1,%2,%3};" \
        : "+f"(d[0]),"+f"(d[1]),"+f"(d[2]),"+f"(d[3]) \
        : "r"(a0),"r"(a1),"r"(a2),"r"(a3),"r"(b0),"r"(b1))

// ================= TF32 GEMM, register-staged double buffering =============
#define G1_STAGE 8960
#define G1_SMEM  (2 * G1_STAGE * 4)

__global__ void __launch_bounds__(256) gemm_tf32_db_kernel(
    const float* __restrict__ A, const float* __restrict__ B,
    float* __restrict__ C, int M, int N, int K)
{
    extern __shared__ uint32_t sm[];

    const int tid  = threadIdx.x;
    const int warp = tid >> 5;
    const int lane = tid & 31;
    const int grp  = lane >> 2;
    const int tig  = lane & 3;
    const int warp_m = warp & 3;
    const int warp_n = warp >> 2;

    const int brow = blockIdx.y, bcol = blockIdx.x;

    const float* Ap = A + (size_t)brow * 128 * K;
    const float* Bp = B + bcol * 128;

    float acc[2][8][4];
#pragma unroll
    for (int mt = 0; mt < 2; mt++)
#pragma unroll
        for (int nt = 0; nt < 8; nt++)
#pragma unroll
            for (int i = 0; i < 4; i++) acc[mt][nt][i] = 0.f;

    float4 ra[4]; float4 rb[4];
#pragma unroll
    for (int i = 0; i < 4; i++) {
        int idx = tid + i * 256;
        ra[i] = *(const float4*)(Ap + (size_t)(idx >> 3) * K + ((idx & 7) * 4));
        rb[i] = *(const float4*)(Bp + (size_t)(idx >> 5) * N + ((idx & 31) * 4));
    }
    {
        uint32_t* As = sm; uint32_t* Bs = sm + 128 * 36;
#pragma unroll
        for (int i = 0; i < 4; i++) {
            int idx = tid + i * 256;
            int r = idx >> 3, c = (idx & 7) * 4;
            uint4 t; t.x = f2tf32(ra[i].x); t.y = f2tf32(ra[i].y);
            t.z = f2tf32(ra[i].z); t.w = f2tf32(ra[i].w);
            *(uint4*)&As[r * 36 + c] = t;
            int r2 = idx >> 5, c2 = (idx & 31) * 4;
            uint4 u; u.x = f2tf32(rb[i].x); u.y = f2tf32(rb[i].y);
            u.z = f2tf32(rb[i].z); u.w = f2tf32(rb[i].w);
            *(uint4*)&Bs[r2 * 136 + c2] = u;
        }
    }
    __syncthreads();

    const int nk = K >> 5;
    for (int kt = 0; kt < nk; kt++) {
        if (kt + 1 < nk) {
            int k0 = (kt + 1) << 5;
#pragma unroll
            for (int i = 0; i < 4; i++) {
                int idx = tid + i * 256;
                ra[i] = *(const float4*)(Ap + (size_t)(idx >> 3) * K + k0 + ((idx & 7) * 4));
                rb[i] = *(const float4*)(Bp + (size_t)(k0 + (idx >> 5)) * N + ((idx & 31) * 4));
            }
        }
        {
            uint32_t* As = sm + (kt & 1) * G1_STAGE;
            uint32_t* Bs = As + 128 * 36;
#pragma unroll
            for (int ks = 0; ks < 4; ks++) {
                int kb = ks * 8;
                uint32_t af[2][4], bf[8][2];
#pragma unroll
                for (int mt = 0; mt < 2; mt++) {
                    int row0 = warp_m * 32 + mt * 16 + grp;
                    af[mt][0] = As[row0 * 36 + kb + tig];
                    af[mt][1] = As[(row0 + 8) * 36 + kb + tig];
                    af[mt][2] = As[row0 * 36 + kb + 4 + tig];
                    af[mt][3] = As[(row0 + 8) * 36 + kb + 4 + tig];
                }
#pragma unroll
                for (int nt = 0; nt < 8; nt++) {
                    int colw = warp_n * 64 + nt * 8 + grp;
                    bf[nt][0] = Bs[(kb + tig) * 136 + colw];
                    bf[nt][1] = Bs[(kb + 4 + tig) * 136 + colw];
                }
#pragma unroll
                for (int mt = 0; mt < 2; mt++)
#pragma unroll
                    for (int nt = 0; nt < 8; nt++)
                        MMA_TF32(acc[mt][nt], af[mt][0], af[mt][1], af[mt][2], af[mt][3],
                                 bf[nt][0], bf[nt][1]);
            }
        }
        if (kt + 1 < nk) {
            uint32_t* As = sm + ((kt + 1) & 1) * G1_STAGE;
            uint32_t* Bs = As + 128 * 36;
#pragma unroll
            for (int i = 0; i < 4; i++) {
                int idx = tid + i * 256;
                int r = idx >> 3, c = (idx & 7) * 4;
                uint4 t; t.x = f2tf32(ra[i].x); t.y = f2tf32(ra[i].y);
                t.z = f2tf32(ra[i].z); t.w = f2tf32(ra[i].w);
                *(uint4*)&As[r * 36 + c] = t;
                int r2 = idx >> 5, c2 = (idx & 31) * 4;
                uint4 u; u.x = f2tf32(rb[i].x); u.y = f2tf32(rb[i].y);
                u.z = f2tf32(rb[i].z); u.w = f2tf32(rb[i].w);
                *(uint4*)&Bs[r2 * 136 + c2] = u;
            }
        }
        __syncthreads();
    }

#pragma unroll
    for (int mt = 0; mt < 2; mt++) {
        int row = brow * 128 + warp_m * 32 + mt * 16 + grp;
#pragma unroll
        for (int nt = 0; nt < 8; nt++) {
            int col = bcol * 128 + warp_n * 64 + nt * 8 + tig * 2;
            *(float2*)(C + (size_t)row * N + col) =
                make_float2(acc[mt][nt][0], acc[mt][nt][1]);
            *(float2*)(C + (size_t)(row + 8) * N + col) =
                make_float2(acc[mt][nt][2], acc[mt][nt][3]);
        }
    }
}

// ---------------- RoPE (in place) ----------------
__global__ void rope_kernel(float* __restrict__ buf,
                            const float* __restrict__ cosf,
                            const float* __restrict__ sinf,
                            int heads)
{
    int idx = blockIdx.x * blockDim.x + threadIdx.x;
    int total = MM * heads * (HD / 2);
    if (idx >= total) return;
    int i   = idx & 63;
    int t   = idx >> 6;
    int h   = t % heads;
    int row = t / heads;
    int s   = row & (SS - 1);
    float c  = cosf[s * 64 + i];
    float sn = sinf[s * 64 + i];
    float* p = buf + (size_t)row * heads * HD + h * HD + 2 * i;
    float x1 = p[0], x2 = p[1];
    p[0] = x1 * c - x2 * sn;
    p[1] = x1 * sn + x2 * c;
}

// ---------------- cache write-back ----------------
__global__ void cache_kernel(const float* __restrict__ kbuf,
                             const float* __restrict__ vbuf,
                             const float* __restrict__ ck_in,
                             const float* __restrict__ cv_in,
                             float* __restrict__ out_ck,
                             float* __restrict__ out_cv)
{
    int idx = blockIdx.x * blockDim.x + threadIdx.x;
    const int total = BB * SWW * KVH * HD;
    if (idx >= total) return;
    int d = idx & 1023;
    int t = (idx >> 10) & (SWW - 1);
    int b = idx >> 22;
    float ck = ck_in[idx];
    float cv = cv_in[idx];
    if (t < SS) {
        float xk = kbuf[(size_t)(b * SS + t) * (KVH * HD) + d];
        float xv = vbuf[(size_t)(b * SS + t) * (KVH * HD) + d];
        ck = (xk != 0.f) ? xk : ck;
        cv = (xv != 0.f) ? xv : cv;
    }
    out_ck[idx] = ck;
    out_cv[idx] = cv;
}

// ---------------- tensor-core flash attention (causal) ----------------
// Br=128 (8 warps x 16 rows), Bc=32.
// QK^T: split-bf16 (3x m16n8k16) — halves QK MMA issue vs tf32x3.
// PV: single tf32 m16n8k8, V stored NATIVE [c][d] (no transpose).
// K/V of next tile prefetched into registers during compute.
// smem words: Qh 128*68, Ql 128*68, Kh 32*68, Kl 32*68, Vs 32*136, Ps 128*36
#define FL_SMEM_BYTES ((128*68*2 + 32*68*2 + 32*136 + 128*36) * 4)  // 122880

__global__ void __launch_bounds__(256, 1) flash_tc_kernel(
    const float* __restrict__ q, const float* __restrict__ k,
    const float* __restrict__ v, float* __restrict__ o_out)
{
    extern __shared__ uint32_t sh[];
    uint32_t* Qh = sh;                    // 128*68 (bf16x2 words)
    uint32_t* Ql = Qh + 128 * 68;
    uint32_t* Kh = Ql + 128 * 68;         // 32*68
    uint32_t* Kl = Kh + 32 * 68;
    uint32_t* Vs = Kl + 32 * 68;          // 32*136 (tf32, native [c][d])
    uint32_t* Ps = Vs + 32 * 136;         // 128*36

    const int qb  = gridDim.x - 1 - blockIdx.x;   // heavy blocks first
    const int h   = blockIdx.y, b = blockIdx.z;
    const int kvh = h >> 2;
    const int tid = threadIdx.x, warp = tid >> 5, lane = tid & 31;
    const int grp = lane >> 2, tig = lane & 3;
    const int w16 = warp * 16;
    const int rbase = qb * 128;

    const float* kg = k + (size_t)(b * SS) * (KVH * HD) + kvh * HD;
    const float* vg = v + (size_t)(b * SS) * (KVH * HD) + kvh * HD;

    // ---- load Q tile (scaled, split hi/lo bf16) ----
    {
        const float* qg = q + ((size_t)(b * SS) + rbase) * (HH * HD) + h * HD;
#pragma unroll
        for (int i = 0; i < 16; i++) {
            int f = tid + i * 256;
            int r = f >> 5, c4 = (f & 31) * 4;
            float4 t4 = *(const float4*)(qg + (size_t)r * (HH * HD) + c4);
            float x0 = t4.x * SCALE, x1 = t4.y * SCALE, x2 = t4.z * SCALE, x3 = t4.w * SCALE;
            float h0 = bf16_round(x0), h1 = bf16_round(x1);
            float h2 = bf16_round(x2), h3 = bf16_round(x3);
            uint2 wh = make_uint2(pack_bf16(h0, h1), pack_bf16(h2, h3));
            uint2 wl = make_uint2(pack_bf16(x0 - h0, x1 - h1), pack_bf16(x2 - h2, x3 - h3));
            *(uint2*)&Qh[r * 68 + (f & 31) * 2] = wh;
            *(uint2*)&Ql[r * 68 + (f & 31) * 2] = wl;
        }
    }

    float O[16][4];
#pragma unroll
    for (int nf = 0; nf < 16; nf++)
#pragma unroll
        for (int i = 0; i < 4; i++) O[nf][i] = 0.f;
    float m0 = -INFINITY, m1 = -INFINITY, l0 = 0.f, l1 = 0.f;

    // prefetch registers for K and V tiles
    float4 kr[4], vr[4];
    const int fr = tid >> 5, fc4 = (tid & 31) * 4, fw2 = (tid & 31) * 2;

    // ---- prologue: tile 0 into regs, then smem ----
#pragma unroll
    for (int i = 0; i < 4; i++) {
        int r = fr + i * 8;
        kr[i] = *(const float4*)(kg + (size_t)r * (KVH * HD) + fc4);
        vr[i] = *(const float4*)(vg + (size_t)r * (KVH * HD) + fc4);
    }
#pragma unroll
    for (int i = 0; i < 4; i++) {
        int r = fr + i * 8;
        float h0 = bf16_round(kr[i].x), h1 = bf16_round(kr[i].y);
        float h2 = bf16_round(kr[i].z), h3 = bf16_round(kr[i].w);
        *(uint2*)&Kh[r * 68 + fw2] = make_uint2(pack_bf16(h0, h1), pack_bf16(h2, h3));
        *(uint2*)&Kl[r * 68 + fw2] = make_uint2(pack_bf16(kr[i].x - h0, kr[i].y - h1),
                                                pack_bf16(kr[i].z - h2, kr[i].w - h3));
        uint4 vv; vv.x = f2tf32(vr[i].x); vv.y = f2tf32(vr[i].y);
        vv.z = f2tf32(vr[i].z); vv.w = f2tf32(vr[i].w);
        *(uint4*)&Vs[r * 136 + fc4] = vv;
    }
    __syncthreads();

    const int ntiles = (qb + 1) * 4;
    for (int t = 0; t < ntiles; t++) {
        // ---- issue prefetch of tile t+1 ----
        if (t + 1 < ntiles) {
            int tc = (t + 1) * 32;
#pragma unroll
            for (int i = 0; i < 4; i++) {
                int r = tc + fr + i * 8;
                kr[i] = *(const float4*)(kg + (size_t)r * (KVH * HD) + fc4);
                vr[i] = *(const float4*)(vg + (size_t)r * (KVH * HD) + fc4);
            }
        }

        // ---- S = Q @ K^T (split-bf16, 3 MMAs per frag) ----
        float sacc[4][4];
#pragma unroll
        for (int nf = 0; nf < 4; nf++)
#pragma unroll
            for (int i = 0; i < 4; i++) sacc[nf][i] = 0.f;

#pragma unroll
        for (int ks = 0; ks < 8; ks++) {
            int kb = ks * 8;
            int ra0 = (w16 + grp) * 68 + kb + tig;
            int ra1 = (w16 + grp + 8) * 68 + kb + tig;
            uint32_t qh0 = Qh[ra0], qh1 = Qh[ra1], qh2 = Qh[ra0 + 4], qh3 = Qh[ra1 + 4];
            uint32_t ql0 = Ql[ra0], ql1 = Ql[ra1], ql2 = Ql[ra0 + 4], ql3 = Ql[ra1 + 4];
#pragma unroll
            for (int nf = 0; nf < 4; nf++) {
                int rb = (nf * 8 + grp) * 68 + kb + tig;
                uint32_t kh0 = Kh[rb], kh1 = Kh[rb + 4];
                uint32_t kl0 = Kl[rb], kl1 = Kl[rb + 4];
                MMA_BF16(sacc[nf], qh0, qh1, qh2, qh3, kh0, kh1);
                MMA_BF16(sacc[nf], qh0, qh1, qh2, qh3, kl0, kl1);
                MMA_BF16(sacc[nf], ql0, ql1, ql2, ql3, kh0, kh1);
            }
        }

        // ---- causal mask ----
        int tc0 = t * 32;
        if (t >= 4 * qb) {
            int row0 = rbase + w16 + grp, row1 = row0 + 8;
#pragma unroll
            for (int nf = 0; nf < 4; nf++) {
                int col = tc0 + nf * 8 + 2 * tig;
                if (col     > row0) sacc[nf][0] = NEGV;
                if (col + 1 > row0) sacc[nf][1] = NEGV;
                if (col     > row1) sacc[nf][2] = NEGV;
                if (col + 1 > row1) sacc[nf][3] = NEGV;
            }
        }

        // ---- online softmax ----
        float mx0 = -INFINITY, mx1 = -INFINITY;
#pragma unroll
        for (int nf = 0; nf < 4; nf++) {
            mx0 = fmaxf(mx0, fmaxf(sacc[nf][0], sacc[nf][1]));
            mx1 = fmaxf(mx1, fmaxf(sacc[nf][2], sacc[nf][3]));
        }
        mx0 = fmaxf(mx0, __shfl_xor_sync(0xffffffffu, mx0, 1));
        mx0 = fmaxf(mx0, __shfl_xor_sync(0xffffffffu, mx0, 2));
        mx1 = fmaxf(mx1, __shfl_xor_sync(0xffffffffu, mx1, 1));
        mx1 = fmaxf(mx1, __shfl_xor_sync(0xffffffffu, mx1, 2));

        float nm0 = fmaxf(m0, mx0), nm1 = fmaxf(m1, mx1);
        float cr0 = __expf(m0 - nm0), cr1 = __expf(m1 - nm1);
        float s0 = 0.f, s1 = 0.f;
        int pr0 = (w16 + grp) * 36 + 2 * tig;
        int pr1 = (w16 + grp + 8) * 36 + 2 * tig;
#pragma unroll
        for (int nf = 0; nf < 4; nf++) {
            float p0 = __expf(sacc[nf][0] - nm0);
            float p1 = __expf(sacc[nf][1] - nm0);
            float p2 = __expf(sacc[nf][2] - nm1);
            float p3 = __expf(sacc[nf][3] - nm1);
            s0 += p0 + p1; s1 += p2 + p3;
            Ps[pr0 + nf * 8]     = f2tf32(p0);
            Ps[pr0 + nf * 8 + 1] = f2tf32(p1);
            Ps[pr1 + nf * 8]     = f2tf32(p2);
            Ps[pr1 + nf * 8 + 1] = f2tf32(p3);
        }
        s0 += __shfl_xor_sync(0xffffffffu, s0, 1);
        s0 += __shfl_xor_sync(0xffffffffu, s0, 2);
        s1 += __shfl_xor_sync(0xffffffffu, s1, 1);
        s1 += __shfl_xor_sync(0xffffffffu, s1, 2);
        l0 = l0 * cr0 + s0;
        l1 = l1 * cr1 + s1;
        m0 = nm0; m1 = nm1;
#pragma unroll
        for (int nf = 0; nf < 16; nf++) {
            O[nf][0] *= cr0; O[nf][1] *= cr0;
            O[nf][2] *= cr1; O[nf][3] *= cr1;
        }
        __syncwarp();

        // ---- O += P @ V (V native layout [c][d]) ----
#pragma unroll
        for (int ks = 0; ks < 4; ks++) {
            int kb = ks * 8;
            int rp0 = (w16 + grp) * 36 + kb + tig;
            int rp1 = (w16 + grp + 8) * 36 + kb + tig;
            uint32_t pa0 = Ps[rp0], pa1 = Ps[rp1], pa2 = Ps[rp0 + 4], pa3 = Ps[rp1 + 4];
#pragma unroll
            for (int nf = 0; nf < 16; nf++) {
                int n = nf * 8 + grp;
                uint32_t b0 = Vs[(kb + tig) * 136 + n];
                uint32_t b1 = Vs[(kb + tig + 4) * 136 + n];
                MMA_TF32(O[nf], pa0, pa1, pa2, pa3, b0, b1);
            }
        }

        // ---- commit prefetched tile ----
        __syncthreads();
        if (t + 1 < ntiles) {
#pragma unroll
            for (int i = 0; i < 4; i++) {
                int r = fr + i * 8;
                float h0 = bf16_round(kr[i].x), h1 = bf16_round(kr[i].y);
                float h2 = bf16_round(kr[i].z), h3 = bf16_round(kr[i].w);
                *(uint2*)&Kh[r * 68 + fw2] = make_uint2(pack_bf16(h0, h1), pack_bf16(h2, h3));
                *(uint2*)&Kl[r * 68 + fw2] = make_uint2(pack_bf16(kr[i].x - h0, kr[i].y - h1),
                                                        pack_bf16(kr[i].z - h2, kr[i].w - h3));
                uint4 vv; vv.x = f2tf32(vr[i].x); vv.y = f2tf32(vr[i].y);
                vv.z = f2tf32(vr[i].z); vv.w = f2tf32(vr[i].w);
                *(uint4*)&Vs[r * 136 + fc4] = vv;
            }
            __syncthreads();
        }
    }

    // ---- epilogue ----
    float inv0 = 1.f / l0, inv1 = 1.f / l1;
    float* og = o_out + ((size_t)(b * SS) + rbase + w16) * (HH * HD) + h * HD;
#pragma unroll
    for (int nf = 0; nf < 16; nf++) {
        int col = nf * 8 + 2 * tig;
        *(float2*)(og + (size_t)grp * (HH * HD) + col) =
            make_float2(O[nf][0] * inv0, O[nf][1] * inv0);
        *(float2*)(og + (size_t)(grp + 8) * (HH * HD) + col) =
            make_float2(O[nf][2] * inv1, O[nf][3] * inv1);
    }
}

// ---------------- launch ----------------
extern "C" void kernel_launch(void* const* d_in, const int* in_sizes, int n_in,
                              void* d_out, int out_size)
{
    const float* x    = (const float*)d_in[0];
    const float* cosf = (const float*)d_in[1];
    const float* sinf = (const float*)d_in[2];
    const float* ck_in = (const float*)d_in[5];
    const float* cv_in = (const float*)d_in[6];
    const float* wq   = (const float*)d_in[7];
    const float* wk   = (const float*)d_in[8];
    const float* wv   = (const float*)d_in[9];
    const float* wo   = (const float*)d_in[10];

    float* out   = (float*)d_out;
    float* outck = out + (size_t)MM * (HH * HD);
    float* outcv = outck + (size_t)BB * SWW * KVH * HD;

    float* q = nullptr; cudaGetSymbolAddress((void**)&q, g_q);
    float* k = nullptr; cudaGetSymbolAddress((void**)&k, g_k);
    float* v = nullptr; cudaGetSymbolAddress((void**)&v, g_v);
    float* a = nullptr; cudaGetSymbolAddress((void**)&a, g_attn);

    static bool attr_done = false;
    if (!attr_done) {
        cudaFuncSetAttribute(flash_tc_kernel,
                             cudaFuncAttributeMaxDynamicSharedMemorySize, FL_SMEM_BYTES);
        cudaFuncSetAttribute(gemm_tf32_db_kernel,
                             cudaFuncAttributeMaxDynamicSharedMemorySize, G1_SMEM);
        attr_done = true;
    }

    // QKV projections (single-pass tf32, double-buffered)
    gemm_tf32_db_kernel<<<dim3((HH*HD)/128,  MM/128), 256, G1_SMEM>>>(x, wq, q, MM, HH*HD, DD);
    gemm_tf32_db_kernel<<<dim3((KVH*HD)/128, MM/128), 256, G1_SMEM>>>(x, wk, k, MM, KVH*HD, DD);
    gemm_tf32_db_kernel<<<dim3((KVH*HD)/128, MM/128), 256, G1_SMEM>>>(x, wv, v, MM, KVH*HD, DD);

    // RoPE
    {
        int tq = MM * HH * 64;
        rope_kernel<<<(tq + 255) / 256, 256>>>(q, cosf, sinf, HH);
        int tk = MM * KVH * 64;
        rope_kernel<<<(tk + 255) / 256, 256>>>(k, cosf, sinf, KVH);
    }

    // KV cache write-back
    {
        int total = BB * SWW * KVH * HD;
        cache_kernel<<<(total + 255) / 256, 256>>>(k, v, ck_in, cv_in, outck, outcv);
    }

    // tensor-core causal flash attention
    flash_tc_kernel<<<dim3(SS / 128, HH, BB), 256, FL_SMEM_BYTES>>>(q, k, v, a);

    // output projection (single-pass tf32, double-buffered)
    gemm_tf32_db_kernel<<<dim3((HH*HD)/128, MM/128), 256, G1_SMEM>>>(a, wo, out, MM, HH*HD, DD);
}